// round 1
// baseline (speedup 1.0000x reference)
#include <cuda_runtime.h>

#define BB    4
#define CC    64
#define HWN   16384
#define NHEAD 8
#define DD    72
#define PART  16

// ---- scratch (static __device__, no allocation) ----
__device__ float g_q[BB*CC*HWN];        // relu(q)  [b][c][n]
__device__ float g_k[BB*CC*HWN];        // relu(k)
__device__ float g_v[BB*CC*HWN];        // v
__device__ float g_kv[BB*NHEAD*DD*DD];  // kv matrices
__device__ float g_ksum[BB*NHEAD*DD];   // k column sums
__device__ float g_o[BB*576*HWN];       // out_unf [b][576][n]
__device__ float g_y1[BB*CC*HWN];       // folded / counts
__device__ float g_wt[9*CC*CC];         // proj weights transposed [slot][c][o]

// ============================================================
// Kernel A: qkv 1x1 conv + bias + relu(q,k). Block = 32 px, 192 outputs.
// ============================================================
__global__ void qkv_kernel(const float* __restrict__ x,
                           const float* __restrict__ w,
                           const float* __restrict__ bias) {
    __shared__ float xs[32*32];     // [c_chunk][px]
    __shared__ float ws[32*192];    // [c_chunk][o]  (transposed)
    int b  = blockIdx.x >> 9;
    int n0 = (blockIdx.x & 511) << 5;
    int tid = threadIdx.x;
    int px = tid & 31;
    int og = tid >> 5;          // 0..7
    int obase = og * 24;
    float acc[24];
#pragma unroll
    for (int i = 0; i < 24; i++) acc[i] = 0.f;

    for (int ch = 0; ch < 2; ch++) {
        int c0 = ch * 32;
        for (int idx = tid; idx < 32*192; idx += 256) {
            int cc = idx / 192, o = idx - cc*192;
            ws[idx] = w[o*64 + c0 + cc];
        }
        for (int idx = tid; idx < 1024; idx += 256) {
            int cc = idx >> 5, p = idx & 31;
            xs[idx] = x[(b*64 + c0 + cc)*HWN + n0 + p];
        }
        __syncthreads();
#pragma unroll 8
        for (int cc = 0; cc < 32; cc++) {
            float xv = xs[cc*32 + px];
            const float4* wr = (const float4*)&ws[cc*192 + obase];
#pragma unroll
            for (int k = 0; k < 6; k++) {
                float4 w4 = wr[k];
                acc[k*4+0] += xv * w4.x;
                acc[k*4+1] += xv * w4.y;
                acc[k*4+2] += xv * w4.z;
                acc[k*4+3] += xv * w4.w;
            }
        }
        __syncthreads();
    }
#pragma unroll
    for (int k = 0; k < 24; k++) {
        int o = obase + k;
        float val = acc[k] + bias[o];
        int n = n0 + px;
        if (o < 64)       g_q[(b*64 + o      )*HWN + n] = fmaxf(val, 0.f);
        else if (o < 128) g_k[(b*64 + (o-64) )*HWN + n] = fmaxf(val, 0.f);
        else              g_v[(b*64 + (o-128))*HWN + n] = val;
    }
}

// ============================================================
// zero kv/ksum accumulators (every launch — graph replays)
// ============================================================
__global__ void zero_kernel() {
    int idx = blockIdx.x*256 + threadIdx.x;
    if (idx < BB*NHEAD*DD*DD) g_kv[idx] = 0.f;
    if (idx < BB*NHEAD*DD)    g_ksum[idx] = 0.f;
}

// transpose proj weights: g_wt[slot][c][o] = w_proj[o][c][slot]
__global__ void wt_kernel(const float* __restrict__ wp) {
    int idx = blockIdx.x*256 + threadIdx.x;   // < 9*4096
    int slot = idx >> 12;
    int rem  = idx & 4095;
    int c = rem >> 6, o = rem & 63;
    g_wt[idx] = wp[o*576 + c*9 + slot];
}

// ============================================================
// Kernel B: kv[d1][d2] += sum_n k_unf[n,d1]*v_unf[n,d2]; ksum[d] += ...
// Block = (b, h, N-partition of 1024 px). 16x16 threads x 5x5 register tile.
// ============================================================
__global__ void kv_kernel() {
    __shared__ float ks[80*33];
    __shared__ float vs[80*33];
    int bi = blockIdx.x;
    int b = bi / (NHEAD*PART);
    int h = (bi / PART) % NHEAD;
    int part = bi % PART;
    int nstart = part * (HWN/PART);
    int tid = threadIdx.x;

    // pad rows 72..79 stay zero forever
    for (int idx = tid; idx < 8*33; idx += 256) {
        ks[72*33 + idx] = 0.f;
        vs[72*33 + idx] = 0.f;
    }
    int rb = tid >> 4, cb = tid & 15;
    int r0 = rb*5, c0 = cb*5;
    float acc[5][5];
#pragma unroll
    for (int i = 0; i < 5; i++)
#pragma unroll
        for (int j = 0; j < 5; j++) acc[i][j] = 0.f;
    float lks = 0.f;
    int kbase = (b*64 + h*8)*HWN;

    for (int t = 0; t < (HWN/PART)/32; t++) {
        int n0 = nstart + t*32;
        __syncthreads();
        for (int idx = tid; idx < 72*32; idx += 256) {
            int d = idx >> 5, p = idx & 31;
            int cpr = d / 9, pp = d - cpr*9;
            int n = n0 + p;
            int y = n >> 7, xx = n & 127;
            int sy = y + pp/3 - 1, sx = xx + (pp%3) - 1;
            bool ok = ((unsigned)sy < 128u) && ((unsigned)sx < 128u);
            int gi = kbase + cpr*HWN + sy*128 + sx;
            ks[d*33 + p] = ok ? g_k[gi] : 0.f;
            vs[d*33 + p] = ok ? g_v[gi] : 0.f;
        }
        __syncthreads();
        if (tid < 72) {
#pragma unroll 8
            for (int p = 0; p < 32; p++) lks += ks[tid*33 + p];
        }
        for (int p = 0; p < 32; p++) {
            float a[5], bv[5];
#pragma unroll
            for (int q = 0; q < 5; q++) {
                a[q]  = ks[(r0+q)*33 + p];
                bv[q] = vs[(c0+q)*33 + p];
            }
#pragma unroll
            for (int i = 0; i < 5; i++)
#pragma unroll
                for (int j = 0; j < 5; j++) acc[i][j] += a[i]*bv[j];
        }
    }
    int base = (b*NHEAD + h)*DD*DD;
#pragma unroll
    for (int i = 0; i < 5; i++) {
        int r = r0 + i;
        if (r >= DD) break;
#pragma unroll
        for (int j = 0; j < 5; j++) {
            int c = c0 + j;
            if (c < DD) atomicAdd(&g_kv[base + r*DD + c], acc[i][j]);
        }
    }
    if (tid < 72) atomicAdd(&g_ksum[(b*NHEAD + h)*DD + tid], lks);
}

// ============================================================
// Kernel C: out_unf[n,e] = (q_unf[n,:] @ kv[:,e]) / (q_unf[n,:].ksum + eps)
// Block = (b, h, 64-px tile). kv + q tile in SMEM.
// ============================================================
__global__ void attn_kernel() {
    __shared__ float kvs[72*74];
    __shared__ float qs[72*65];
    __shared__ float ksum_s[72];
    int bi = blockIdx.x;
    int b = bi >> 11;
    int h = (bi >> 8) & 7;
    int n0 = (bi & 255) << 6;
    int tid = threadIdx.x;

    int kvbase = (b*NHEAD + h)*DD*DD;
    for (int idx = tid; idx < DD*DD; idx += 256) {
        int d = idx / 72, e = idx - d*72;
        kvs[d*74 + e] = g_kv[kvbase + idx];
    }
    if (tid < 72) ksum_s[tid] = g_ksum[(b*NHEAD + h)*DD + tid];

    int qbase = (b*64 + h*8)*HWN;
    for (int idx = tid; idx < 72*64; idx += 256) {
        int d = idx >> 6, p = idx & 63;
        int cpr = d / 9, pp = d - cpr*9;
        int n = n0 + p;
        int y = n >> 7, xx = n & 127;
        int sy = y + pp/3 - 1, sx = xx + (pp%3) - 1;
        bool ok = ((unsigned)sy < 128u) && ((unsigned)sx < 128u);
        qs[d*65 + p] = ok ? g_q[qbase + cpr*HWN + sy*128 + sx] : 0.f;
    }
    __syncthreads();

    int px = tid & 63;
    int eg = tid >> 6;          // 0..3
    int ebase = eg * 18;
    float acc[18];
#pragma unroll
    for (int k = 0; k < 18; k++) acc[k] = 0.f;
    float den = 1e-6f;

    for (int d = 0; d < 72; d++) {
        float qv = qs[d*65 + px];
        den += qv * ksum_s[d];
        const float2* kr = (const float2*)&kvs[d*74 + ebase];
#pragma unroll
        for (int k = 0; k < 9; k++) {
            float2 f = kr[k];
            acc[2*k  ] += qv * f.x;
            acc[2*k+1] += qv * f.y;
        }
    }
    float inv = 1.f / den;
    int obase = (b*576 + h*72 + ebase)*HWN + n0 + px;
#pragma unroll
    for (int k = 0; k < 18; k++)
        g_o[obase + k*HWN] = acc[k] * inv;
}

// ============================================================
// Kernel D: fold + divide by counts
// ============================================================
__global__ void fold_kernel() {
    int idx = blockIdx.x*256 + threadIdx.x;
    int b = idx >> 20;
    int c = (idx >> 14) & 63;
    int n = idx & 16383;
    int Y = n >> 7, X = n & 127;
    float sum = 0.f;
    int cnt = 0;
#pragma unroll
    for (int i = 0; i < 3; i++)
#pragma unroll
        for (int j = 0; j < 3; j++) {
            int sy = Y + 1 - i, sx = X + 1 - j;
            if ((unsigned)sy < 128u && (unsigned)sx < 128u) {
                cnt++;
                sum += g_o[(b*576 + c*9 + i*3 + j)*HWN + sy*128 + sx];
            }
        }
    g_y1[idx] = sum / (float)cnt;
}

// ============================================================
// Kernel E: 3x3 proj conv + bias. 9 shifted 64x64 GEMM passes.
// ============================================================
__global__ void conv_kernel(float* __restrict__ out,
                            const float* __restrict__ bproj) {
    __shared__ float ws2[64*64];    // [c][o] for current (ky,kx)
    __shared__ float xs[64*32];     // [c][px] shifted input
    int b  = blockIdx.x >> 9;
    int n0 = (blockIdx.x & 511) << 5;
    int tid = threadIdx.x;
    int px = tid & 31, og = tid >> 5;
    int obase = og * 8;
    float acc[8];
#pragma unroll
    for (int k = 0; k < 8; k++) acc[k] = 0.f;

    for (int slot = 0; slot < 9; slot++) {
        int ky = slot / 3, kx = slot - ky*3;
        __syncthreads();
        for (int idx = tid; idx < 4096; idx += 256)
            ws2[idx] = g_wt[slot*4096 + idx];
        for (int idx = tid; idx < 2048; idx += 256) {
            int c = idx >> 5, p = idx & 31;
            int n = n0 + p;
            int y = n >> 7, xx = n & 127;
            int sy = y + ky - 1, sx = xx + kx - 1;
            xs[idx] = ((unsigned)sy < 128u && (unsigned)sx < 128u)
                      ? g_y1[(b*64 + c)*HWN + sy*128 + sx] : 0.f;
        }
        __syncthreads();
#pragma unroll 8
        for (int c = 0; c < 64; c++) {
            float xv = xs[c*32 + px];
            const float4* wr = (const float4*)&ws2[c*64 + obase];
            float4 w0 = wr[0], w1 = wr[1];
            acc[0] += xv*w0.x; acc[1] += xv*w0.y;
            acc[2] += xv*w0.z; acc[3] += xv*w0.w;
            acc[4] += xv*w1.x; acc[5] += xv*w1.y;
            acc[6] += xv*w1.z; acc[7] += xv*w1.w;
        }
    }
#pragma unroll
    for (int k = 0; k < 8; k++) {
        int o = obase + k;
        out[(b*64 + o)*HWN + n0 + px] = acc[k] + bproj[o];
    }
}

// ============================================================
extern "C" void kernel_launch(void* const* d_in, const int* in_sizes, int n_in,
                              void* d_out, int out_size) {
    const float* x      = (const float*)d_in[0];
    const float* w_qkv  = (const float*)d_in[1];
    const float* b_qkv  = (const float*)d_in[2];
    const float* w_proj = (const float*)d_in[3];
    const float* b_proj = (const float*)d_in[4];
    float* out = (float*)d_out;

    qkv_kernel<<<2048, 256>>>(x, w_qkv, b_qkv);
    zero_kernel<<<648, 256>>>();
    wt_kernel<<<144, 256>>>(w_proj);
    kv_kernel<<<BB*NHEAD*PART, 256>>>();
    attn_kernel<<<BB*NHEAD*256, 256>>>();
    fold_kernel<<<BB*CC*HWN/256, 256>>>();
    conv_kernel<<<2048, 256>>>(out, b_proj);
}

// round 7
// speedup vs baseline: 1.3190x; 1.3190x over previous
#include <cuda_runtime.h>
#include <cuda_bf16.h>
#include <cstdint>

#define BB    4
#define CC    64
#define HWN   16384
#define NHEAD 8
#define DD    72
#define PART  16

// ---- scratch (static __device__, no allocation) ----
__device__ unsigned g_qhl[BB*CC*HWN];   // bf16 hi (low16) | lo (high16) of relu(q)
__device__ unsigned g_khl[BB*CC*HWN];
__device__ unsigned g_vhl[BB*CC*HWN];
__device__ float g_kv[BB*NHEAD*DD*DD];
__device__ float g_ksum[BB*NHEAD*DD];
__device__ float g_o[BB*576*HWN];
__device__ float g_y1[BB*CC*HWN];
__device__ float g_wt[9*CC*CC];

__device__ __forceinline__ unsigned pack_hl(float v) {
    __nv_bfloat16 h = __float2bfloat16(v);
    float lf = v - __bfloat162float(h);
    __nv_bfloat16 l = __float2bfloat16(lf);
    return (unsigned)__bfloat16_as_ushort(h) | ((unsigned)__bfloat16_as_ushort(l) << 16);
}

// m16n8k16 bf16 mma, fp32 accum. A row-major, B col-major.
__device__ __forceinline__ void mma16816(float* c, const unsigned* a, const unsigned* b) {
    asm volatile(
        "mma.sync.aligned.m16n8k16.row.col.f32.bf16.bf16.f32 "
        "{%0,%1,%2,%3}, {%4,%5,%6,%7}, {%8,%9}, {%0,%1,%2,%3};"
        : "+f"(c[0]), "+f"(c[1]), "+f"(c[2]), "+f"(c[3])
        : "r"(a[0]), "r"(a[1]), "r"(a[2]), "r"(a[3]), "r"(b[0]), "r"(b[1]));
}

__device__ __forceinline__ unsigned ldu(const unsigned short* p, int elem) {
    return *(const unsigned*)(p + elem);   // elem must be even
}

// ============================================================
// Kernel A: qkv 1x1 conv + bias + relu(q,k) -> packed bf16 hi/lo
// ============================================================
__global__ void qkv_kernel(const float* __restrict__ x,
                           const float* __restrict__ w,
                           const float* __restrict__ bias) {
    __shared__ float xs[32*32];
    __shared__ float ws[32*192];
    int b  = blockIdx.x >> 9;
    int n0 = (blockIdx.x & 511) << 5;
    int tid = threadIdx.x;
    int px = tid & 31;
    int og = tid >> 5;
    int obase = og * 24;
    float acc[24];
#pragma unroll
    for (int i = 0; i < 24; i++) acc[i] = 0.f;

    for (int ch = 0; ch < 2; ch++) {
        int c0 = ch * 32;
        for (int idx = tid; idx < 32*192; idx += 256) {
            int cc = idx / 192, o = idx - cc*192;
            ws[idx] = w[o*64 + c0 + cc];
        }
        for (int idx = tid; idx < 1024; idx += 256) {
            int cc = idx >> 5, p = idx & 31;
            xs[idx] = x[(b*64 + c0 + cc)*HWN + n0 + p];
        }
        __syncthreads();
#pragma unroll 8
        for (int cc = 0; cc < 32; cc++) {
            float xv = xs[cc*32 + px];
            const float4* wr = (const float4*)&ws[cc*192 + obase];
#pragma unroll
            for (int k = 0; k < 6; k++) {
                float4 w4 = wr[k];
                acc[k*4+0] += xv * w4.x;
                acc[k*4+1] += xv * w4.y;
                acc[k*4+2] += xv * w4.z;
                acc[k*4+3] += xv * w4.w;
            }
        }
        __syncthreads();
    }
    int n = n0 + px;
#pragma unroll
    for (int k = 0; k < 24; k++) {
        int o = obase + k;
        float val = acc[k] + bias[o];
        if (o < 64)       g_qhl[(b*64 + o      )*HWN + n] = pack_hl(fmaxf(val, 0.f));
        else if (o < 128) g_khl[(b*64 + (o-64) )*HWN + n] = pack_hl(fmaxf(val, 0.f));
        else              g_vhl[(b*64 + (o-128))*HWN + n] = pack_hl(val);
    }
}

__global__ void zero_kernel() {
    int idx = blockIdx.x*256 + threadIdx.x;
    if (idx < BB*NHEAD*DD*DD) g_kv[idx] = 0.f;
    if (idx < BB*NHEAD*DD)    g_ksum[idx] = 0.f;
}

__global__ void wt_kernel(const float* __restrict__ wp) {
    int idx = blockIdx.x*256 + threadIdx.x;
    int slot = idx >> 12;
    int rem  = idx & 4095;
    int c = rem >> 6, o = rem & 63;
    g_wt[idx] = wp[o*576 + c*9 + slot];
}

// ============================================================
// Kernel B (warp mma): kv[d1][d2] += sum_n k[n,d1] v[n,d2]; ksum via ones col.
// Tiles [80][64tok] bf16 stride 72 (conflict-free). 320 thr = 10 warps,
// each warp: one 16-row m-tile half x five 8-col n-tiles. M=80,N=80,K=1024/CTA.
// ============================================================
#define KVSTR 72
#define KVTHREADS 320
__global__ void kv_kernel() {
    __shared__ unsigned short ksh[80*KVSTR];
    __shared__ unsigned short ksl[80*KVSTR];
    __shared__ unsigned short vsh[80*KVSTR];
    __shared__ unsigned short vsl[80*KVSTR];

    int tid = threadIdx.x, wid = tid >> 5, lane = tid & 31;
    int bi = blockIdx.x;
    int b = bi / (NHEAD*PART);
    int h = (bi / PART) % NHEAD;
    int part = bi % PART;
    int nstart = part * (HWN/PART);       // 1024 tokens per CTA

    // balanced warp -> tile map: 5 m-tiles x (2 half-ranges of 5 n-tiles)
    int mt = wid >> 1;
    int ntBase = (wid & 1)*5;

    // zero pad rows 72..79; ones row (d2=72) in vsh for ksum
    for (int idx = tid; idx < 8*64; idx += KVTHREADS) {
        int r = 72 + (idx >> 6), j = idx & 63;
        ksh[r*KVSTR + j] = 0; ksl[r*KVSTR + j] = 0;
        vsh[r*KVSTR + j] = (r == 72) ? (unsigned short)0x3F80 : (unsigned short)0;
        vsl[r*KVSTR + j] = 0;
    }

    float acc[5][4];
#pragma unroll
    for (int i = 0; i < 5; i++)
#pragma unroll
        for (int j = 0; j < 4; j++) acc[i][j] = 0.f;

    int gbase = (b*64 + h*8)*HWN;
    int ly = lane >> 2, lx2 = (lane & 3)*2;

    for (int t = 0; t < (HWN/PART)/64; t++) {
        __syncthreads();
        int n0 = nstart + t*64;
        for (int idx = tid; idx < 72*64; idx += KVTHREADS) {
            int d = idx >> 6, j = idx & 63;
            int cpr = d / 9, pp = d - cpr*9;
            int n = n0 + j;
            int y = n >> 7, xx = n & 127;
            int sy = y + pp/3 - 1, sx = xx + (pp%3) - 1;
            unsigned uk = 0, uv = 0;
            if ((unsigned)sy < 128u && (unsigned)sx < 128u) {
                int gi = gbase + cpr*HWN + sy*128 + sx;
                uk = g_khl[gi];
                uv = g_vhl[gi];
            }
            int e = d*KVSTR + j;
            ksh[e] = (unsigned short)(uk & 0xFFFF);
            ksl[e] = (unsigned short)(uk >> 16);
            vsh[e] = (unsigned short)(uv & 0xFFFF);
            vsl[e] = (unsigned short)(uv >> 16);
        }
        __syncthreads();
#pragma unroll
        for (int kk = 0; kk < 4; kk++) {
            int ar = mt*16 + ly;
            int ac = kk*16 + lx2;
            unsigned ah[4], al[4];
            ah[0] = ldu(ksh, ar*KVSTR + ac);       ah[1] = ldu(ksh, (ar+8)*KVSTR + ac);
            ah[2] = ldu(ksh, ar*KVSTR + ac + 8);   ah[3] = ldu(ksh, (ar+8)*KVSTR + ac + 8);
            al[0] = ldu(ksl, ar*KVSTR + ac);       al[1] = ldu(ksl, (ar+8)*KVSTR + ac);
            al[2] = ldu(ksl, ar*KVSTR + ac + 8);   al[3] = ldu(ksl, (ar+8)*KVSTR + ac + 8);
#pragma unroll
            for (int i = 0; i < 5; i++) {
                int br = (ntBase + i)*8 + ly;
                unsigned bh[2], bl[2];
                bh[0] = ldu(vsh, br*KVSTR + ac);
                bh[1] = ldu(vsh, br*KVSTR + ac + 8);
                bl[0] = ldu(vsl, br*KVSTR + ac);
                bl[1] = ldu(vsl, br*KVSTR + ac + 8);
                mma16816(acc[i], ah, bh);
                mma16816(acc[i], al, bh);
                mma16816(acc[i], ah, bl);
            }
        }
    }

    // epilogue: atomics into g_kv / g_ksum
    int base = (b*NHEAD + h)*DD*DD;
    int r0 = mt*16 + ly, r1 = r0 + 8;
#pragma unroll
    for (int i = 0; i < 5; i++) {
        int e = (ntBase + i)*8 + lx2;
        if (r0 < 72) {
            if (e < 72)       atomicAdd(&g_kv[base + r0*DD + e], acc[i][0]);
            else if (e == 72) atomicAdd(&g_ksum[(b*NHEAD + h)*DD + r0], acc[i][0]);
            if (e + 1 < 72)   atomicAdd(&g_kv[base + r0*DD + e + 1], acc[i][1]);
        }
        if (r1 < 72) {
            if (e < 72)       atomicAdd(&g_kv[base + r1*DD + e], acc[i][2]);
            else if (e == 72) atomicAdd(&g_ksum[(b*NHEAD + h)*DD + r1], acc[i][2]);
            if (e + 1 < 72)   atomicAdd(&g_kv[base + r1*DD + e + 1], acc[i][3]);
        }
    }
}

// ============================================================
// Kernel C (warp mma): out[n,e] = (q_unf[n,:] @ kv[:,e]) / (q.ksum + eps)
// A = q [128tok x 80d] stride 88; B = kvT+ksum [80e x 80d] stride 88.
// 8 warps: warp = one 16-row m-tile, 10 n-tiles each.
// ============================================================
#define ATSTR 88
#define AT_QH 0
#define AT_QL (128*ATSTR*2)
#define AT_BH (2*128*ATSTR*2)
#define AT_BL (2*128*ATSTR*2 + 80*ATSTR*2)
#define AT_SMEM (2*128*ATSTR*2 + 2*80*ATSTR*2)
#define OSTR 132

__global__ void attn_kernel() {
    extern __shared__ char smem[];
    unsigned short* qh = (unsigned short*)(smem + AT_QH);
    unsigned short* ql = (unsigned short*)(smem + AT_QL);
    unsigned short* Bh = (unsigned short*)(smem + AT_BH);
    unsigned short* Bl = (unsigned short*)(smem + AT_BL);
    float* outs = (float*)smem;           // overlays q region after compute

    int tid = threadIdx.x, wid = tid >> 5, lane = tid & 31;
    int bi = blockIdx.x;
    int b = bi >> 10;
    int h = (bi >> 7) & 7;
    int n0 = (bi & 127) << 7;

    // zero q pad cols / B region
    for (int idx = tid; idx < 128*ATSTR/2; idx += 256) {
        ((unsigned*)qh)[idx] = 0; ((unsigned*)ql)[idx] = 0;
    }
    for (int idx = tid; idx < 80*ATSTR/2; idx += 256) {
        ((unsigned*)Bh)[idx] = 0; ((unsigned*)Bl)[idx] = 0;
    }
    __syncthreads();

    // fill A: q tile
    int gbase = (b*64 + h*8)*HWN;
    for (int idx = tid; idx < 72*128; idx += 256) {
        int px = idx & 127, d = idx >> 7;
        int cpr = d / 9, pp = d - cpr*9;
        int n = n0 + px;
        int y = n >> 7, xx = n & 127;
        int sy = y + pp/3 - 1, sx = xx + (pp%3) - 1;
        unsigned u = 0;
        if ((unsigned)sy < 128u && (unsigned)sx < 128u)
            u = g_qhl[gbase + cpr*HWN + sy*128 + sx];
        qh[px*ATSTR + d] = (unsigned short)(u & 0xFFFF);
        ql[px*ATSTR + d] = (unsigned short)(u >> 16);
    }
    // fill B: rows e 0..71 from kv^T, row 72 = ksum
    int kvb = (b*NHEAD + h)*DD*DD;
    int ksb = (b*NHEAD + h)*DD;
    for (int idx = tid; idx < 73*72; idx += 256) {
        int e = idx / 72, d = idx - e*72;
        float v = (e < 72) ? g_kv[kvb + d*DD + e] : g_ksum[ksb + d];
        unsigned u = pack_hl(v);
        Bh[e*ATSTR + d] = (unsigned short)(u & 0xFFFF);
        Bl[e*ATSTR + d] = (unsigned short)(u >> 16);
    }
    __syncthreads();

    int ly = lane >> 2, lx2 = (lane & 3)*2;
    float acc[10][4];
#pragma unroll
    for (int i = 0; i < 10; i++)
#pragma unroll
        for (int j = 0; j < 4; j++) acc[i][j] = 0.f;

    int ar = wid*16 + ly;
#pragma unroll
    for (int kk = 0; kk < 5; kk++) {
        int ac = kk*16 + lx2;
        unsigned ah[4], al[4];
        ah[0] = ldu(qh, ar*ATSTR + ac);       ah[1] = ldu(qh, (ar+8)*ATSTR + ac);
        ah[2] = ldu(qh, ar*ATSTR + ac + 8);   ah[3] = ldu(qh, (ar+8)*ATSTR + ac + 8);
        al[0] = ldu(ql, ar*ATSTR + ac);       al[1] = ldu(ql, (ar+8)*ATSTR + ac);
        al[2] = ldu(ql, ar*ATSTR + ac + 8);   al[3] = ldu(ql, (ar+8)*ATSTR + ac + 8);
#pragma unroll
        for (int i = 0; i < 10; i++) {
            int br = i*8 + ly;
            unsigned bh[2], bl[2];
            bh[0] = ldu(Bh, br*ATSTR + ac);
            bh[1] = ldu(Bh, br*ATSTR + ac + 8);
            bl[0] = ldu(Bl, br*ATSTR + ac);
            bl[1] = ldu(Bl, br*ATSTR + ac + 8);
            mma16816(acc[i], ah, bh);
            mma16816(acc[i], al, bh);
            mma16816(acc[i], ah, bl);
        }
    }

    // denominators: e=72 lives in n-tile 9 at local col 0 (lanes with lane&3==0)
    float den0 = __shfl_sync(0xffffffffu, acc[9][0], lane & ~3);
    float den1 = __shfl_sync(0xffffffffu, acc[9][2], lane & ~3);
    float inv0 = 1.f / (den0 + 1e-6f);
    float inv1 = 1.f / (den1 + 1e-6f);

    __syncthreads();   // tiles dead; reuse smem for output staging
    int r0 = wid*16 + ly, r1 = r0 + 8;
#pragma unroll
    for (int i = 0; i < 9; i++) {
        int e = i*8 + lx2;
        outs[e*OSTR + r0]     = acc[i][0] * inv0;
        outs[(e+1)*OSTR + r0] = acc[i][1] * inv0;
        outs[e*OSTR + r1]     = acc[i][2] * inv1;
        outs[(e+1)*OSTR + r1] = acc[i][3] * inv1;
    }
    __syncthreads();
    int ob = (b*576 + h*72)*HWN + n0;
    for (int idx = tid; idx < 72*128; idx += 256) {
        int e = idx >> 7, t = idx & 127;
        g_o[ob + e*HWN + t] = outs[e*OSTR + t];
    }
}

// ============================================================
// Kernel D: fold + divide by counts
// ============================================================
__global__ void fold_kernel() {
    int idx = blockIdx.x*256 + threadIdx.x;
    int b = idx >> 20;
    int c = (idx >> 14) & 63;
    int n = idx & 16383;
    int Y = n >> 7, X = n & 127;
    float sum = 0.f;
    int cnt = 0;
#pragma unroll
    for (int i = 0; i < 3; i++)
#pragma unroll
        for (int j = 0; j < 3; j++) {
            int sy = Y + 1 - i, sx = X + 1 - j;
            if ((unsigned)sy < 128u && (unsigned)sx < 128u) {
                cnt++;
                sum += g_o[(b*576 + c*9 + i*3 + j)*HWN + sy*128 + sx];
            }
        }
    g_y1[idx] = sum / (float)cnt;
}

// ============================================================
// Kernel E: 3x3 proj conv + bias
// ============================================================
__global__ void conv_kernel(float* __restrict__ out,
                            const float* __restrict__ bproj) {
    __shared__ float ws2[64*64];
    __shared__ float xs[64*32];
    int b  = blockIdx.x >> 9;
    int n0 = (blockIdx.x & 511) << 5;
    int tid = threadIdx.x;
    int px = tid & 31, og = tid >> 5;
    int obase = og * 8;
    float acc[8];
#pragma unroll
    for (int k = 0; k < 8; k++) acc[k] = 0.f;

    for (int slot = 0; slot < 9; slot++) {
        int ky = slot / 3, kx = slot - ky*3;
        __syncthreads();
        for (int idx = tid; idx < 4096; idx += 256)
            ws2[idx] = g_wt[slot*4096 + idx];
        for (int idx = tid; idx < 2048; idx += 256) {
            int c = idx >> 5, p = idx & 31;
            int n = n0 + p;
            int y = n >> 7, xx = n & 127;
            int sy = y + ky - 1, sx = xx + kx - 1;
            xs[idx] = ((unsigned)sy < 128u && (unsigned)sx < 128u)
                      ? g_y1[(b*64 + c)*HWN + sy*128 + sx] : 0.f;
        }
        __syncthreads();
#pragma unroll 8
        for (int c = 0; c < 64; c++) {
            float xv = xs[c*32 + px];
            const float4* wr = (const float4*)&ws2[c*64 + obase];
            float4 w0 = wr[0], w1 = wr[1];
            acc[0] += xv*w0.x; acc[1] += xv*w0.y;
            acc[2] += xv*w0.z; acc[3] += xv*w0.w;
            acc[4] += xv*w1.x; acc[5] += xv*w1.y;
            acc[6] += xv*w1.z; acc[7] += xv*w1.w;
        }
    }
#pragma unroll
    for (int k = 0; k < 8; k++) {
        int o = obase + k;
        out[(b*64 + o)*HWN + n0 + px] = acc[k] + bproj[o];
    }
}

// ============================================================
extern "C" void kernel_launch(void* const* d_in, const int* in_sizes, int n_in,
                              void* d_out, int out_size) {
    const float* x      = (const float*)d_in[0];
    const float* w_qkv  = (const float*)d_in[1];
    const float* b_qkv  = (const float*)d_in[2];
    const float* w_proj = (const float*)d_in[3];
    const float* b_proj = (const float*)d_in[4];
    float* out = (float*)d_out;

    cudaFuncSetAttribute(attn_kernel, cudaFuncAttributeMaxDynamicSharedMemorySize, AT_SMEM);

    qkv_kernel<<<2048, 256>>>(x, w_qkv, b_qkv);
    zero_kernel<<<648, 256>>>();
    wt_kernel<<<144, 256>>>(w_proj);
    kv_kernel<<<BB*NHEAD*PART, KVTHREADS>>>();
    attn_kernel<<<BB*NHEAD*128, 256, AT_SMEM>>>();
    fold_kernel<<<BB*CC*HWN/256, 256>>>();
    conv_kernel<<<2048, 256>>>(out, b_proj);
}